// round 4
// baseline (speedup 1.0000x reference)
#include <cuda_runtime.h>
#include <cstdint>

#define BATCH   8
#define NPTS    16384
#define CH      13
#define NGROUP  512
#define KNN     32

#define FPS_CLUSTER 4
#define FPS_THREADS 256
#define FPS_PPT     (NPTS / FPS_CLUSTER / FPS_THREADS)   // 16 points per thread

#define KT      512                 // knn threads per block
#define KPT     (NPTS / KT)         // 32 points per thread

#define NEIGH_ELEMS ((size_t)BATCH * NGROUP * KNN * CH)  // 1,703,936
#define CEN_ELEMS   ((size_t)BATCH * NGROUP * 3)         // 12,288

// Static device scratch (no allocation allowed).
__device__ float4 g_pts[BATCH * NPTS];          // x,y,z,pp  (2 MB)
__device__ float  g_centers[BATCH * NGROUP * 3];

// ---------------------------------------------------------------------------
// Prep: pack xyz (channels 4:7) + pp = ((x^2+y^2)+z^2) (non-FMA, XLA order)
// ---------------------------------------------------------------------------
__global__ void prep_kernel(const float* __restrict__ x) {
    int i = blockIdx.x * blockDim.x + threadIdx.x;
    if (i >= BATCH * NPTS) return;
    const float* p = x + (size_t)i * CH;
    float px = p[4], py = p[5], pz = p[6];
    float pp = __fadd_rn(__fadd_rn(__fmul_rn(px, px), __fmul_rn(py, py)),
                         __fmul_rn(pz, pz));
    g_pts[i] = make_float4(px, py, pz, pp);
}

__device__ __forceinline__ uint32_t smem_u32(const void* p) {
    return (uint32_t)__cvta_generic_to_shared(p);
}

// ---------------------------------------------------------------------------
// FPS: one 4-CTA cluster per batch. Points + min_d live in registers.
// Per iteration: local update+argmax, warp/CTA reduce, DSMEM all-to-all
// exchange of packed (min_d_bits<<32 | (N - idx)) keys, 1 cluster.sync
// (double-buffered slots).
// Distance = ((dx*dx + dy*dy) + dz*dz) with explicit rn intrinsics (no FMA
// contraction) to match XLA's fusion; argmax tie-break = smallest index.
// ---------------------------------------------------------------------------
__global__ void __cluster_dims__(FPS_CLUSTER, 1, 1) __launch_bounds__(FPS_THREADS, 1)
fps_kernel() {
    __shared__ unsigned long long warpbest[FPS_THREADS / 32];
    __shared__ unsigned long long exch[2][FPS_CLUSTER];

    uint32_t rank;
    asm("mov.u32 %0, %%cluster_ctarank;" : "=r"(rank));
    int b = blockIdx.x / FPS_CLUSTER;
    int t = threadIdx.x;
    int w = t >> 5;
    const float4* pts = g_pts + (size_t)b * NPTS;
    int base = (int)rank * (NPTS / FPS_CLUSTER) + t * FPS_PPT;

    float px[FPS_PPT], py[FPS_PPT], pz[FPS_PPT], md[FPS_PPT];
#pragma unroll
    for (int k = 0; k < FPS_PPT; k++) {
        float4 p = pts[base + k];
        px[k] = p.x; py[k] = p.y; pz[k] = p.z;
        md[k] = 1e10f;   // matches reference init 10000000000.0
    }

    float* cout = g_centers + (size_t)b * NGROUP * 3;
    if (rank == 0 && t == 0) {
        float4 c0 = pts[0];
        cout[0] = c0.x; cout[1] = c0.y; cout[2] = c0.z;
    }

    int last = 0;
    for (int g = 1; g < NGROUP; g++) {
        float4 lp = pts[last];   // uniform broadcast load, L1-resident
        float bv = -1.0f;
        int   bi = base;
#pragma unroll
        for (int k = 0; k < FPS_PPT; k++) {
            float dx = px[k] - lp.x;
            float dy = py[k] - lp.y;
            float dz = pz[k] - lp.z;
            float d  = __fadd_rn(__fadd_rn(__fmul_rn(dx, dx), __fmul_rn(dy, dy)),
                                 __fmul_rn(dz, dz));
            float m = fminf(md[k], d);
            md[k] = m;
            if (m > bv) { bv = m; bi = base + k; }  // strict > keeps smallest idx
        }
        // pack: value-major (non-negative float bits monotonic), tie -> smaller idx
        unsigned long long key =
            ((unsigned long long)__float_as_uint(bv) << 32) | (uint32_t)(NPTS - bi);
#pragma unroll
        for (int o = 16; o > 0; o >>= 1) {
            unsigned long long ok = __shfl_down_sync(0xFFFFFFFFu, key, o);
            if (ok > key) key = ok;
        }
        if ((t & 31) == 0) warpbest[w] = key;
        __syncthreads();
        if (t == 0) {
            unsigned long long kb = warpbest[0];
#pragma unroll
            for (int i = 1; i < FPS_THREADS / 32; i++) {
                unsigned long long v = warpbest[i];
                if (v > kb) kb = v;
            }
            int p = g & 1;
            uint32_t laddr = smem_u32(&exch[p][rank]);
#pragma unroll
            for (uint32_t r = 0; r < FPS_CLUSTER; r++) {
                uint32_t raddr;
                asm("mapa.shared::cluster.u32 %0, %1, %2;" : "=r"(raddr)
                    : "r"(laddr), "r"(r));
                asm volatile("st.shared::cluster.u64 [%0], %1;"
                             :: "r"(raddr), "l"(kb) : "memory");
            }
        }
        asm volatile("barrier.cluster.arrive.aligned;" ::: "memory");
        asm volatile("barrier.cluster.wait.aligned;" ::: "memory");
        {
            int p = g & 1;
            unsigned long long kb = exch[p][0];
#pragma unroll
            for (int i = 1; i < FPS_CLUSTER; i++) {
                unsigned long long v = exch[p][i];
                if (v > kb) kb = v;
            }
            last = NPTS - (uint32_t)(kb & 0xFFFFFFFFull);
        }
        if (rank == 0 && t == 0) {
            float4 cp = pts[last];
            cout[g * 3 + 0] = cp.x;
            cout[g * 3 + 1] = cp.y;
            cout[g * 3 + 2] = cp.z;
        }
    }
}

// ---------------------------------------------------------------------------
// KNN + gather. One block per (batch, group). d2 mapped to order-preserving
// u32 keys in smem; 32 iterative argmin passes with cached per-thread and
// per-warp minima (only the owner rescans its 32 keys per pass).
// d2 = (cc + pp) - 2*dot, dot = fma(cz,pz, fma(cy,py, cx*px))  [cuBLAS-order
// FP32 hypothesis]. Tie-break everywhere: smaller index first (top_k stable).
// ---------------------------------------------------------------------------
__global__ void __launch_bounds__(KT)
knn_kernel(const float* __restrict__ x, float* __restrict__ out_neigh) {
    extern __shared__ uint32_t skey[];          // NPTS ordered keys (64 KB)
    __shared__ uint32_t wk[KT / 32];
    __shared__ uint32_t wi[KT / 32];
    __shared__ uint32_t sel[KNN];
    __shared__ uint32_t s_win;

    int b  = blockIdx.y;
    int gq = blockIdx.x;
    int t = threadIdx.x, w = t >> 5, lane = t & 31;
    const float4* pts = g_pts + (size_t)b * NPTS;
    const float* c3 = g_centers + ((size_t)b * NGROUP + gq) * 3;
    float cx = c3[0], cy = c3[1], cz = c3[2];
    float cc = __fadd_rn(__fadd_rn(__fmul_rn(cx, cx), __fmul_rn(cy, cy)),
                         __fmul_rn(cz, cz));

    uint32_t tk = 0xFFFFFFFFu, ti = 0xFFFFFFFFu;   // thread-local min (key, idx)
#pragma unroll
    for (int kk = 0; kk < KPT; kk++) {
        int i = kk * KT + t;
        float4 p = pts[i];
        float dot = __fmaf_rn(cz, p.z, __fmaf_rn(cy, p.y, __fmul_rn(cx, p.x)));
        float d2  = __fsub_rn(__fadd_rn(cc, p.w), __fmul_rn(2.0f, dot));
        uint32_t u = __float_as_uint(d2);
        uint32_t o = u ^ (uint32_t)(((int)u >> 31) | 0x80000000);  // order-preserving
        skey[i] = o;
        if (o < tk) { tk = o; ti = (uint32_t)i; }  // strict <, i ascending
    }
    // per-warp min
    {
        uint32_t rk = tk, ri = ti;
#pragma unroll
        for (int off = 16; off > 0; off >>= 1) {
            uint32_t ok = __shfl_down_sync(0xFFFFFFFFu, rk, off);
            uint32_t oi = __shfl_down_sync(0xFFFFFFFFu, ri, off);
            if (ok < rk || (ok == rk && oi < ri)) { rk = ok; ri = oi; }
        }
        if (lane == 0) { wk[w] = rk; wi[w] = ri; }
    }
    __syncthreads();

    for (int j = 0; j < KNN; j++) {
        if (w == 0) {
            uint32_t ak = (lane < KT / 32) ? wk[lane] : 0xFFFFFFFFu;
            uint32_t ai = (lane < KT / 32) ? wi[lane] : 0xFFFFFFFFu;
#pragma unroll
            for (int off = 16; off > 0; off >>= 1) {
                uint32_t ok = __shfl_down_sync(0xFFFFFFFFu, ak, off);
                uint32_t oi = __shfl_down_sync(0xFFFFFFFFu, ai, off);
                if (ok < ak || (ok == ak && oi < ai)) { ak = ok; ai = oi; }
            }
            if (lane == 0) { sel[j] = ai; s_win = ai; }
        }
        __syncthreads();
        uint32_t widx = s_win;
        int owner = (int)(widx & (KT - 1));
        if (t == owner) {
            skey[widx] = 0xFFFFFFFFu;
            tk = 0xFFFFFFFFu; ti = 0xFFFFFFFFu;
#pragma unroll
            for (int kk = 0; kk < KPT; kk++) {
                int i = kk * KT + t;
                uint32_t o = skey[i];
                if (o < tk) { tk = o; ti = (uint32_t)i; }
            }
        }
        if (w == (owner >> 5)) {
            uint32_t rk = tk, ri = ti;
#pragma unroll
            for (int off = 16; off > 0; off >>= 1) {
                uint32_t ok = __shfl_down_sync(0xFFFFFFFFu, rk, off);
                uint32_t oi = __shfl_down_sync(0xFFFFFFFFu, ri, off);
                if (ok < rk || (ok == rk && oi < ri)) { rk = ok; ri = oi; }
            }
            if (lane == 0) { wk[w] = rk; wi[w] = ri; }
        }
        __syncthreads();
    }

    // gather 32 x 13 features; channels 4..6 get (+ (-center)) like the reference
    if (t < KNN * CH) {
        int jj = t / CH, c = t % CH;
        uint32_t idx = sel[jj];
        float v = x[((size_t)b * NPTS + idx) * CH + c];
        if (c >= 4 && c < 7) {
            float cv = (c == 4) ? cx : ((c == 5) ? cy : cz);
            v = __fadd_rn(v, -cv);
        }
        out_neigh[(((size_t)b * NGROUP + gq) * KNN + jj) * CH + c] = v;
    }
}

// Copy centers scratch -> output tail
__global__ void centers_out_kernel(float* __restrict__ out_cen) {
    int i = blockIdx.x * blockDim.x + threadIdx.x;
    if (i < (int)CEN_ELEMS) out_cen[i] = g_centers[i];
}

extern "C" void kernel_launch(void* const* d_in, const int* in_sizes, int n_in,
                              void* d_out, int out_size) {
    const float* x = (const float*)d_in[0];
    float* out = (float*)d_out;

    cudaFuncSetAttribute(knn_kernel, cudaFuncAttributeMaxDynamicSharedMemorySize,
                         NPTS * sizeof(uint32_t));

    prep_kernel<<<(BATCH * NPTS + 255) / 256, 256>>>(x);
    fps_kernel<<<BATCH * FPS_CLUSTER, FPS_THREADS>>>();
    knn_kernel<<<dim3(NGROUP, BATCH), KT, NPTS * sizeof(uint32_t)>>>(x, out);
    if ((size_t)out_size >= NEIGH_ELEMS + CEN_ELEMS) {
        centers_out_kernel<<<((int)CEN_ELEMS + 255) / 256, 256>>>(out + NEIGH_ELEMS);
    }
}

// round 5
// speedup vs baseline: 1.2121x; 1.2121x over previous
#include <cuda_runtime.h>
#include <cstdint>

#define BATCH   8
#define NPTS    16384
#define CH      13
#define NGROUP  512
#define KNN     32

#define FPS_CLUSTER 8
#define FPS_THREADS 256
#define FPS_CHUNK   (NPTS / FPS_CLUSTER)            // 2048 points per CTA
#define FPS_PPT     (FPS_CHUNK / FPS_THREADS)       // 8 points per thread
#define FPS_PAIRS   (FPS_PPT / 2)                   // 4 packed pairs

#define KT      512                 // knn threads per block
#define KPT     (NPTS / KT)         // 32 points per thread

#define NEIGH_ELEMS ((size_t)BATCH * NGROUP * KNN * CH)  // 1,703,936
#define CEN_ELEMS   ((size_t)BATCH * NGROUP * 3)         // 12,288

// Static device scratch (no allocation allowed).
__device__ float4 g_pts[BATCH * NPTS];          // x,y,z,pp  (2 MB)
__device__ float  g_centers[BATCH * NGROUP * 3];

// ---------------------------------------------------------------------------
// Prep: pack xyz (channels 4:7) + pp = ((x^2+y^2)+z^2) (non-FMA, XLA order)
// ---------------------------------------------------------------------------
__global__ void prep_kernel(const float* __restrict__ x) {
    int i = blockIdx.x * blockDim.x + threadIdx.x;
    if (i >= BATCH * NPTS) return;
    const float* p = x + (size_t)i * CH;
    float px = p[4], py = p[5], pz = p[6];
    float pp = __fadd_rn(__fadd_rn(__fmul_rn(px, px), __fmul_rn(py, py)),
                         __fmul_rn(pz, pz));
    g_pts[i] = make_float4(px, py, pz, pp);
}

__device__ __forceinline__ uint32_t smem_u32(const void* p) {
    return (uint32_t)__cvta_generic_to_shared(p);
}
__device__ __forceinline__ unsigned long long pack2(float a, float b) {
    unsigned long long r;
    asm("mov.b64 %0, {%1, %2};" : "=l"(r) : "f"(a), "f"(b));
    return r;
}
__device__ __forceinline__ unsigned long long addx2(unsigned long long a,
                                                    unsigned long long b) {
    unsigned long long r;
    asm("add.rn.f32x2 %0, %1, %2;" : "=l"(r) : "l"(a), "l"(b));
    return r;
}
__device__ __forceinline__ unsigned long long mulx2(unsigned long long a,
                                                    unsigned long long b) {
    unsigned long long r;
    asm("mul.rn.f32x2 %0, %1, %2;" : "=l"(r) : "l"(a), "l"(b));
    return r;
}
__device__ __forceinline__ uint32_t mapa_sh(uint32_t addr, uint32_t r) {
    uint32_t o;
    asm("mapa.shared::cluster.u32 %0, %1, %2;" : "=r"(o) : "r"(addr), "r"(r));
    return o;
}
__device__ __forceinline__ void dsm_st(uint32_t addr, unsigned long long v) {
    asm volatile("st.relaxed.cluster.shared::cluster.u64 [%0], %1;"
                 :: "r"(addr), "l"(v) : "memory");
}
__device__ __forceinline__ unsigned long long poll_ld(uint32_t addr) {
    unsigned long long v;
    asm volatile("ld.relaxed.cluster.shared::cta.u64 %0, [%1];"
                 : "=l"(v) : "r"(addr) : "memory");
    return v;
}

// ---------------------------------------------------------------------------
// FPS: one 8-CTA cluster per batch. Points (packed f32x2) + min_d (raw bits,
// u32) live in registers. Distance = ((dx*dx+dy*dy)+dz*dz) computed with
// add.rn.f32x2 / mul.rn.f32x2 — bit-identical per half to the scalar rn ops
// the reference produces. min/argmax on raw bits (non-negative floats:
// uint order == float order), ties -> smallest index at every level
// (lane order == index order; warps/ranks cover ascending chunks).
// Cross-CTA sync: self-tagged double-buffered DSMEM slots + relaxed spin
// (each u64 word carries the iteration tag in its high half), replacing the
// ~490-cycle cluster barrier. Winner coords ride in the exchange record.
// ---------------------------------------------------------------------------
__global__ void __cluster_dims__(FPS_CLUSTER, 1, 1) __launch_bounds__(FPS_THREADS, 1)
fps_kernel() {
    __shared__ uint32_t s_wval[FPS_THREADS / 32];
    __shared__ int      s_widx[FPS_THREADS / 32];
    // rslot[parity][rank][word]: word0=(tag|val) word1=(tag|x) word2=(tag|y) word3=(tag|z)
    __shared__ unsigned long long rslot[2][FPS_CLUSTER][4];

    uint32_t rank;
    asm("mov.u32 %0, %%cluster_ctarank;" : "=r"(rank));
    int b = blockIdx.x / FPS_CLUSTER;
    int t = threadIdx.x, w = t >> 5, lane = t & 31;
    const float4* pts = g_pts + (size_t)b * NPTS;
    int base = (int)rank * FPS_CHUNK + t * FPS_PPT;

    // init all slot tags to an impossible value before any peer can store
    if (t < 2 * FPS_CLUSTER * 4) {
        ((unsigned long long*)rslot)[t] = ~0ull;
    }

    const uint32_t MD0 = __float_as_uint(1e10f);
    unsigned long long pxp[FPS_PAIRS], pyp[FPS_PAIRS], pzp[FPS_PAIRS];
    uint32_t md[FPS_PPT];
#pragma unroll
    for (int j = 0; j < FPS_PAIRS; j++) {
        float4 p0 = pts[base + 2 * j];
        float4 p1 = pts[base + 2 * j + 1];
        pxp[j] = pack2(p0.x, p1.x);
        pyp[j] = pack2(p0.y, p1.y);
        pzp[j] = pack2(p0.z, p1.z);
        md[2 * j] = MD0;
        md[2 * j + 1] = MD0;
    }

    float4 p00 = pts[0];
    float lx = p00.x, ly = p00.y, lz = p00.z;
    float* cout = g_centers + (size_t)b * NGROUP * 3;
    if (rank == 0 && t == 0) { cout[0] = lx; cout[1] = ly; cout[2] = lz; }

    // one-time cluster barrier: slot init must complete before any peer store
    asm volatile("barrier.cluster.arrive.aligned;" ::: "memory");
    asm volatile("barrier.cluster.wait.aligned;" ::: "memory");

    for (int g = 1; g < NGROUP; g++) {
        int p = g & 1;
        unsigned long long tag = ((unsigned long long)(uint32_t)g) << 32;
        unsigned long long nlx2 = pack2(-lx, -lx);
        unsigned long long nly2 = pack2(-ly, -ly);
        unsigned long long nlz2 = pack2(-lz, -lz);
        uint32_t bv = 0; int bk = base;
#pragma unroll
        for (int j = 0; j < FPS_PAIRS; j++) {
            unsigned long long dx2 = addx2(pxp[j], nlx2);
            unsigned long long dy2 = addx2(pyp[j], nly2);
            unsigned long long dz2 = addx2(pzp[j], nlz2);
            unsigned long long dd  = addx2(addx2(mulx2(dx2, dx2), mulx2(dy2, dy2)),
                                           mulx2(dz2, dz2));
            uint32_t d0 = (uint32_t)dd, d1 = (uint32_t)(dd >> 32);
            uint32_t m0 = umin(md[2 * j], d0);
            md[2 * j] = m0;
            if (m0 > bv) { bv = m0; bk = base + 2 * j; }
            uint32_t m1 = umin(md[2 * j + 1], d1);
            md[2 * j + 1] = m1;
            if (m1 > bv) { bv = m1; bk = base + 2 * j + 1; }
        }
        // warp winner: value via redux, index via ballot (lane order == idx order)
        uint32_t wv = __reduce_max_sync(0xFFFFFFFFu, bv);
        uint32_t mm = __ballot_sync(0xFFFFFFFFu, bv == wv);
        int leader = __ffs((int)mm) - 1;
        int wi = __shfl_sync(0xFFFFFFFFu, bk, leader);
        if (lane == 0) { s_wval[w] = wv; s_widx[w] = wi; }
        __syncthreads();
        if (t == 0) {
            uint32_t cv = s_wval[0]; int ci = s_widx[0];
#pragma unroll
            for (int i = 1; i < FPS_THREADS / 32; i++)
                if (s_wval[i] > cv) { cv = s_wval[i]; ci = s_widx[i]; }
            float4 cp = pts[ci];   // own chunk -> L1 hit
            unsigned long long w0 = tag | cv;
            unsigned long long w1 = tag | __float_as_uint(cp.x);
            unsigned long long w2 = tag | __float_as_uint(cp.y);
            unsigned long long w3 = tag | __float_as_uint(cp.z);
            uint32_t a0 = smem_u32(&rslot[p][rank][0]);
#pragma unroll
            for (uint32_t r = 0; r < FPS_CLUSTER; r++) {
                uint32_t m0a = mapa_sh(a0, r);
                dsm_st(m0a +  8, w1);
                dsm_st(m0a + 16, w2);
                dsm_st(m0a + 24, w3);
                dsm_st(m0a,      w0);   // val word last (readers poll this first)
            }
        }
        // poll all ranks' val words; ascending rank + strict > => smallest
        // global index on value ties (ranks cover ascending chunks)
        uint32_t bestv = 0; int bestr = 0;
#pragma unroll
        for (int r = 0; r < FPS_CLUSTER; r++) {
            uint32_t ap = smem_u32(&rslot[p][r][0]);
            unsigned long long pl;
            do { pl = poll_ld(ap); } while ((uint32_t)(pl >> 32) != (uint32_t)g);
            uint32_t v = (uint32_t)pl;
            if (v > bestv) { bestv = v; bestr = r; }
        }
        // fetch winner coords (each word self-tagged -> no ordering needed)
        {
            uint32_t ab = smem_u32(&rslot[p][bestr][0]);
            unsigned long long w1, w2, w3;
            do { w1 = poll_ld(ab + 8);  } while ((uint32_t)(w1 >> 32) != (uint32_t)g);
            do { w2 = poll_ld(ab + 16); } while ((uint32_t)(w2 >> 32) != (uint32_t)g);
            do { w3 = poll_ld(ab + 24); } while ((uint32_t)(w3 >> 32) != (uint32_t)g);
            lx = __uint_as_float((uint32_t)w1);
            ly = __uint_as_float((uint32_t)w2);
            lz = __uint_as_float((uint32_t)w3);
        }
        if (rank == 0 && t == 0) {
            cout[3 * g] = lx; cout[3 * g + 1] = ly; cout[3 * g + 2] = lz;
        }
    }
}

// ---------------------------------------------------------------------------
// KNN + gather (unchanged from the passing R4 kernel, rel_err == 0).
// ---------------------------------------------------------------------------
__global__ void __launch_bounds__(KT)
knn_kernel(const float* __restrict__ x, float* __restrict__ out_neigh) {
    extern __shared__ uint32_t skey[];          // NPTS ordered keys (64 KB)
    __shared__ uint32_t wk[KT / 32];
    __shared__ uint32_t wi[KT / 32];
    __shared__ uint32_t sel[KNN];
    __shared__ uint32_t s_win;

    int b  = blockIdx.y;
    int gq = blockIdx.x;
    int t = threadIdx.x, w = t >> 5, lane = t & 31;
    const float4* pts = g_pts + (size_t)b * NPTS;
    const float* c3 = g_centers + ((size_t)b * NGROUP + gq) * 3;
    float cx = c3[0], cy = c3[1], cz = c3[2];
    float cc = __fadd_rn(__fadd_rn(__fmul_rn(cx, cx), __fmul_rn(cy, cy)),
                         __fmul_rn(cz, cz));

    uint32_t tk = 0xFFFFFFFFu, ti = 0xFFFFFFFFu;
#pragma unroll
    for (int kk = 0; kk < KPT; kk++) {
        int i = kk * KT + t;
        float4 p = pts[i];
        float dot = __fmaf_rn(cz, p.z, __fmaf_rn(cy, p.y, __fmul_rn(cx, p.x)));
        float d2  = __fsub_rn(__fadd_rn(cc, p.w), __fmul_rn(2.0f, dot));
        uint32_t u = __float_as_uint(d2);
        uint32_t o = u ^ (uint32_t)(((int)u >> 31) | 0x80000000);
        skey[i] = o;
        if (o < tk) { tk = o; ti = (uint32_t)i; }
    }
    {
        uint32_t rk = tk, ri = ti;
#pragma unroll
        for (int off = 16; off > 0; off >>= 1) {
            uint32_t ok = __shfl_down_sync(0xFFFFFFFFu, rk, off);
            uint32_t oi = __shfl_down_sync(0xFFFFFFFFu, ri, off);
            if (ok < rk || (ok == rk && oi < ri)) { rk = ok; ri = oi; }
        }
        if (lane == 0) { wk[w] = rk; wi[w] = ri; }
    }
    __syncthreads();

    for (int j = 0; j < KNN; j++) {
        if (w == 0) {
            uint32_t ak = (lane < KT / 32) ? wk[lane] : 0xFFFFFFFFu;
            uint32_t ai = (lane < KT / 32) ? wi[lane] : 0xFFFFFFFFu;
#pragma unroll
            for (int off = 16; off > 0; off >>= 1) {
                uint32_t ok = __shfl_down_sync(0xFFFFFFFFu, ak, off);
                uint32_t oi = __shfl_down_sync(0xFFFFFFFFu, ai, off);
                if (ok < ak || (ok == ak && oi < ai)) { ak = ok; ai = oi; }
            }
            if (lane == 0) { sel[j] = ai; s_win = ai; }
        }
        __syncthreads();
        uint32_t widx = s_win;
        int owner = (int)(widx & (KT - 1));
        if (t == owner) {
            skey[widx] = 0xFFFFFFFFu;
            tk = 0xFFFFFFFFu; ti = 0xFFFFFFFFu;
#pragma unroll
            for (int kk = 0; kk < KPT; kk++) {
                int i = kk * KT + t;
                uint32_t o = skey[i];
                if (o < tk) { tk = o; ti = (uint32_t)i; }
            }
        }
        if (w == (owner >> 5)) {
            uint32_t rk = tk, ri = ti;
#pragma unroll
            for (int off = 16; off > 0; off >>= 1) {
                uint32_t ok = __shfl_down_sync(0xFFFFFFFFu, rk, off);
                uint32_t oi = __shfl_down_sync(0xFFFFFFFFu, ri, off);
                if (ok < rk || (ok == rk && oi < ri)) { rk = ok; ri = oi; }
            }
            if (lane == 0) { wk[w] = rk; wi[w] = ri; }
        }
        __syncthreads();
    }

    if (t < KNN * CH) {
        int jj = t / CH, c = t % CH;
        uint32_t idx = sel[jj];
        float v = x[((size_t)b * NPTS + idx) * CH + c];
        if (c >= 4 && c < 7) {
            float cv = (c == 4) ? cx : ((c == 5) ? cy : cz);
            v = __fadd_rn(v, -cv);
        }
        out_neigh[(((size_t)b * NGROUP + gq) * KNN + jj) * CH + c] = v;
    }
}

// Copy centers scratch -> output tail
__global__ void centers_out_kernel(float* __restrict__ out_cen) {
    int i = blockIdx.x * blockDim.x + threadIdx.x;
    if (i < (int)CEN_ELEMS) out_cen[i] = g_centers[i];
}

extern "C" void kernel_launch(void* const* d_in, const int* in_sizes, int n_in,
                              void* d_out, int out_size) {
    const float* x = (const float*)d_in[0];
    float* out = (float*)d_out;

    cudaFuncSetAttribute(knn_kernel, cudaFuncAttributeMaxDynamicSharedMemorySize,
                         NPTS * sizeof(uint32_t));

    prep_kernel<<<(BATCH * NPTS + 255) / 256, 256>>>(x);
    fps_kernel<<<BATCH * FPS_CLUSTER, FPS_THREADS>>>();
    knn_kernel<<<dim3(NGROUP, BATCH), KT, NPTS * sizeof(uint32_t)>>>(x, out);
    if ((size_t)out_size >= NEIGH_ELEMS + CEN_ELEMS) {
        centers_out_kernel<<<((int)CEN_ELEMS + 255) / 256, 256>>>(out + NEIGH_ELEMS);
    }
}